// round 8
// baseline (speedup 1.0000x reference)
#include <cuda_runtime.h>
#include <cuda_bf16.h>
#include <cstdint>

#define NB    16
#define NPTS  4096
#define SPTS  1024
#define COLS  65536
#define JCOLS 16384

// fp32 scratch
__device__ __align__(16) float g_Z[3u * 16384u * 256u];   // Z[k][col][o] o-contig
__device__ __align__(16) float g_Y[256u * 65536u];
__device__ __align__(16) float g_O2[128u * 65536u];
// bf16 split weights
__device__ __align__(16) __nv_bfloat16 g_W0Thi[512 * 256], g_W0Tlo[512 * 256];   // [c][o]
__device__ __align__(16) __nv_bfloat16 g_W1Thi[256 * 128], g_W1Tlo[256 * 128];   // [c][o]
__device__ int   g_idx[65536 * 3];
__device__ float g_w[65536 * 3];
__device__ float g_sum0[256], g_sq0[256], g_a0[256], g_c0[256];
__device__ float g_sum1[128], g_sq1[128], g_a1[128], g_c1[128];

__device__ __forceinline__ void cp16(uint32_t dst, const void* src) {
    asm volatile("cp.async.ca.shared.global [%0], [%1], 16;\n" :: "r"(dst), "l"(src));
}
__device__ __forceinline__ void cp_commit() { asm volatile("cp.async.commit_group;\n"); }
template<int N> __device__ __forceinline__ void cp_wait() {
    asm volatile("cp.async.wait_group %0;\n" :: "n"(N));
}
__device__ __forceinline__ void ldsm4t(uint32_t* r, uint32_t addr) {
    asm volatile("ldmatrix.sync.aligned.m8n8.x4.trans.shared.b16 {%0,%1,%2,%3}, [%4];"
                 : "=r"(r[0]), "=r"(r[1]), "=r"(r[2]), "=r"(r[3]) : "r"(addr));
}
__device__ __forceinline__ void mma16816(float* d, const uint32_t* a, const uint32_t* b) {
    asm volatile("mma.sync.aligned.m16n8k16.row.col.f32.bf16.bf16.f32 "
                 "{%0,%1,%2,%3}, {%4,%5,%6,%7}, {%8,%9}, {%0,%1,%2,%3};"
                 : "+f"(d[0]), "+f"(d[1]), "+f"(d[2]), "+f"(d[3])
                 : "r"(a[0]), "r"(a[1]), "r"(a[2]), "r"(a[3]), "r"(b[0]), "r"(b[1]));
}
__device__ __forceinline__ uint32_t bf2u(__nv_bfloat16 a, __nv_bfloat16 b) {
    return (uint32_t)__bfloat16_as_ushort(a) | ((uint32_t)__bfloat16_as_ushort(b) << 16);
}

// smem per CTA (bytes), total 114688:
//   A stages 0..2 : s*16384       (hi 8K at +0, lo 8K at +8192)  [k 32][m 128] bf16 swizzled
//   B raw   0..1  : 49152+s*16384 [k 32][n 128] fp32
//   conv    0..1  : 81920+s*16384 (hi 8K, lo 8K) [k 32][n 128] bf16 swizzled
#define SMEM_BYTES 114688

// Pipelined mainloop. A pre-split bf16 hi/lo (global, row pitch A_LD elements per k),
// B fp32 (global, row pitch B_LD), converted in-smem one tile ahead. NT k-tiles of 32.
// 256 threads, 8 warps: wm = w&3 (m 32), wn = w>>2 (n 64).
template<int A_LD, int B_LD, int NT, bool BN>
__device__ __forceinline__ void mma_main(char* sm,
        const __nv_bfloat16* aHi, const __nv_bfloat16* aLo,
        const float* bF, const float* bnA, const float* bnC,
        float acc[2][8][4]) {
    const int t = threadIdx.x;
    const int L = t & 31, w = t >> 5;
    const int wm = w & 3, wn = w >> 2;
    const uint32_t sb = (uint32_t)__cvta_generic_to_shared(sm);
    const int lk = t >> 3, lg = t & 7;                 // loader: k-row, group
    const uint32_t dA0 = (uint32_t)(lk * 256 + ((lg ^ (lk & 7)) << 4));
    const uint32_t dA1 = (uint32_t)(lk * 256 + (((lg + 8) ^ (lk & 7)) << 4));
    const uint32_t dB  = (uint32_t)(lk * 512 + lg * 16);
    const __nv_bfloat16* pAh = aHi + (size_t)lk * A_LD + lg * 8;
    const __nv_bfloat16* pAl = aLo + (size_t)lk * A_LD + lg * 8;
    const float* pB = bF + (size_t)lk * B_LD + lg * 4;

    uint32_t aoff[2], boff[4];
    {
        const int mtx = L >> 3;
        const int kA = (L & 7) + ((mtx & 2) << 2);
        const int mA = wm * 32 + ((mtx & 1) << 3);
#pragma unroll
        for (int am = 0; am < 2; am++)
            aoff[am] = (uint32_t)(kA * 256 + ((((mA + am * 16) >> 3) ^ (kA & 7)) << 4));
        const int kB = L & 15;
#pragma unroll
        for (int p = 0; p < 4; p++) {
            const int nb = wn * 64 + p * 16 + ((L >> 4) << 3);
            boff[p] = (uint32_t)(kB * 256 + (((nb >> 3) ^ (kB & 7)) << 4));
        }
    }
#pragma unroll
    for (int am = 0; am < 2; am++)
#pragma unroll
        for (int an = 0; an < 8; an++)
#pragma unroll
            for (int d = 0; d < 4; d++) acc[am][an][d] = 0.f;

#define LOAD_AB(kt2) do { \
        const uint32_t ab = sb + ((kt2) % 3) * 16384; \
        const size_t ao = (size_t)(kt2) * 32 * A_LD; \
        cp16(ab + dA0, pAh + ao); \
        cp16(ab + dA1, pAh + ao + 64); \
        cp16(ab + 8192 + dA0, pAl + ao); \
        cp16(ab + 8192 + dA1, pAl + ao + 64); \
        const uint32_t bb2 = sb + 49152 + ((kt2) & 1) * 16384; \
        const size_t bo = (size_t)(kt2) * 32 * B_LD; \
        cp16(bb2 + dB,        pB + bo); \
        cp16(bb2 + dB + 128,  pB + bo + 32); \
        cp16(bb2 + dB + 256,  pB + bo + 64); \
        cp16(bb2 + dB + 384,  pB + bo + 96); \
    } while (0)

    auto convert = [&](int ckt) {
        const char* srcp = sm + 49152 + (ckt & 1) * 16384 + lk * 512 + lg * 64;
        float4 u0 = *(const float4*)srcp;
        float4 u1 = *(const float4*)(srcp + 16);
        float4 u2 = *(const float4*)(srcp + 32);
        float4 u3 = *(const float4*)(srcp + 48);
        if (BN) {
            const int kabs = ckt * 32 + lk;
            const float a = bnA[kabs], c = bnC[kabs];
            u0.x = fmaxf(0.f, fmaf(a, u0.x, c)); u0.y = fmaxf(0.f, fmaf(a, u0.y, c));
            u0.z = fmaxf(0.f, fmaf(a, u0.z, c)); u0.w = fmaxf(0.f, fmaf(a, u0.w, c));
            u1.x = fmaxf(0.f, fmaf(a, u1.x, c)); u1.y = fmaxf(0.f, fmaf(a, u1.y, c));
            u1.z = fmaxf(0.f, fmaf(a, u1.z, c)); u1.w = fmaxf(0.f, fmaf(a, u1.w, c));
            u2.x = fmaxf(0.f, fmaf(a, u2.x, c)); u2.y = fmaxf(0.f, fmaf(a, u2.y, c));
            u2.z = fmaxf(0.f, fmaf(a, u2.z, c)); u2.w = fmaxf(0.f, fmaf(a, u2.w, c));
            u3.x = fmaxf(0.f, fmaf(a, u3.x, c)); u3.y = fmaxf(0.f, fmaf(a, u3.y, c));
            u3.z = fmaxf(0.f, fmaf(a, u3.z, c)); u3.w = fmaxf(0.f, fmaf(a, u3.w, c));
        }
        const __nv_bfloat16 h0 = __float2bfloat16(u0.x), h1 = __float2bfloat16(u0.y);
        const __nv_bfloat16 h2 = __float2bfloat16(u0.z), h3 = __float2bfloat16(u0.w);
        const __nv_bfloat16 h4 = __float2bfloat16(u1.x), h5 = __float2bfloat16(u1.y);
        const __nv_bfloat16 h6 = __float2bfloat16(u1.z), h7 = __float2bfloat16(u1.w);
        const __nv_bfloat16 h8 = __float2bfloat16(u2.x), h9 = __float2bfloat16(u2.y);
        const __nv_bfloat16 ha = __float2bfloat16(u2.z), hb = __float2bfloat16(u2.w);
        const __nv_bfloat16 hc = __float2bfloat16(u3.x), hd = __float2bfloat16(u3.y);
        const __nv_bfloat16 he = __float2bfloat16(u3.z), hf = __float2bfloat16(u3.w);
        uint4 hiA = make_uint4(bf2u(h0, h1), bf2u(h2, h3), bf2u(h4, h5), bf2u(h6, h7));
        uint4 hiB = make_uint4(bf2u(h8, h9), bf2u(ha, hb), bf2u(hc, hd), bf2u(he, hf));
        uint4 loA = make_uint4(
            bf2u(__float2bfloat16(u0.x - __bfloat162float(h0)),
                 __float2bfloat16(u0.y - __bfloat162float(h1))),
            bf2u(__float2bfloat16(u0.z - __bfloat162float(h2)),
                 __float2bfloat16(u0.w - __bfloat162float(h3))),
            bf2u(__float2bfloat16(u1.x - __bfloat162float(h4)),
                 __float2bfloat16(u1.y - __bfloat162float(h5))),
            bf2u(__float2bfloat16(u1.z - __bfloat162float(h6)),
                 __float2bfloat16(u1.w - __bfloat162float(h7))));
        uint4 loB = make_uint4(
            bf2u(__float2bfloat16(u2.x - __bfloat162float(h8)),
                 __float2bfloat16(u2.y - __bfloat162float(h9))),
            bf2u(__float2bfloat16(u2.z - __bfloat162float(ha)),
                 __float2bfloat16(u2.w - __bfloat162float(hb))),
            bf2u(__float2bfloat16(u3.x - __bfloat162float(hc)),
                 __float2bfloat16(u3.y - __bfloat162float(hd))),
            bf2u(__float2bfloat16(u3.z - __bfloat162float(he)),
                 __float2bfloat16(u3.w - __bfloat162float(hf))));
        char* cd = sm + 81920 + (ckt & 1) * 16384 + lk * 256;
        const int g0 = lg * 2;
        *(uint4*)(cd + ((g0 ^ (lk & 7)) << 4)) = hiA;
        *(uint4*)(cd + (((g0 + 1) ^ (lk & 7)) << 4)) = hiB;
        *(uint4*)(cd + 8192 + ((g0 ^ (lk & 7)) << 4)) = loA;
        *(uint4*)(cd + 8192 + (((g0 + 1) ^ (lk & 7)) << 4)) = loB;
    };

    LOAD_AB(0); cp_commit();
    LOAD_AB(1); cp_commit();
    cp_wait<1>();
    __syncthreads();
    convert(0);

#pragma unroll 1
    for (int kt = 0; kt < NT; kt++) {
        cp_wait<0>();
        __syncthreads();                 // conv(kt) visible; raw/conv buffers rotate safely
        if (kt + 1 < NT) convert(kt + 1);
        if (kt + 2 < NT) LOAD_AB(kt + 2);
        cp_commit();
        const uint32_t sA = sb + (kt % 3) * 16384;
        const uint32_t sB = sb + 81920 + (kt & 1) * 16384;
#pragma unroll
        for (int half = 0; half < 2; half++) {
            const uint32_t ksb = half * 4096;
            uint32_t ah[2][4], al[2][4], bb[4];
#pragma unroll
            for (int am = 0; am < 2; am++) {
                ldsm4t(ah[am], sA + aoff[am] + ksb);
                ldsm4t(al[am], sA + 8192 + aoff[am] + ksb);
            }
#pragma unroll
            for (int p = 0; p < 4; p++) {
                ldsm4t(bb, sB + boff[p] + ksb);
#pragma unroll
                for (int am = 0; am < 2; am++) {
                    mma16816(acc[am][2 * p],     ah[am], bb);
                    mma16816(acc[am][2 * p + 1], ah[am], bb + 2);
                    mma16816(acc[am][2 * p],     al[am], bb);
                    mma16816(acc[am][2 * p + 1], al[am], bb + 2);
                }
            }
#pragma unroll
            for (int p = 0; p < 4; p++) {
                ldsm4t(bb, sB + 8192 + boff[p] + ksb);
#pragma unroll
                for (int am = 0; am < 2; am++) {
                    mma16816(acc[am][2 * p],     ah[am], bb);
                    mma16816(acc[am][2 * p + 1], ah[am], bb + 2);
                }
            }
        }
    }
#undef LOAD_AB
}

// ---------------- prep: zero stats + split weights to bf16 hi/lo ----------------
__global__ void prep_kernel(const float* __restrict__ w0, const float* __restrict__ w1) {
    const int idx = blockIdx.x * 256 + threadIdx.x;  // grid 512
    if (idx < 256) { g_sum0[idx] = 0.f; g_sq0[idx] = 0.f; }
    if (idx < 128) { g_sum1[idx] = 0.f; g_sq1[idx] = 0.f; }
    if (idx < 512 * 256) {
        const float v = w0[(idx & 255) * 512 + (idx >> 8)];
        const __nv_bfloat16 h = __float2bfloat16(v);
        g_W0Thi[idx] = h;
        g_W0Tlo[idx] = __float2bfloat16(v - __bfloat162float(h));
    }
    if (idx < 256 * 128) {
        const float v = w1[(idx & 127) * 256 + (idx >> 7)];
        const __nv_bfloat16 h = __float2bfloat16(v);
        g_W1Thi[idx] = h;
        g_W1Tlo[idx] = __float2bfloat16(v - __bfloat162float(h));
    }
}

// ---------------- 3-NN search + interpolation weights ----------------
__global__ void knn_kernel(const float* __restrict__ xyz1,
                           const float* __restrict__ xyz2) {
    __shared__ float sx[SPTS], sy[SPTS], sz[SPTS], sn[SPTS];
    const int t = threadIdx.x;
    const int b = blockIdx.x >> 4;
    const int qbase = (blockIdx.x & 15) << 8;
    const float* base2 = xyz2 + (size_t)b * 3 * SPTS;
    for (int i = t; i < SPTS; i += 256) {
        float x = base2[i], y = base2[SPTS + i], z = base2[2 * SPTS + i];
        sx[i] = x; sy[i] = y; sz[i] = z; sn[i] = x * x + y * y + z * z;
    }
    __syncthreads();
    const int n = qbase + t;
    const float* base1 = xyz1 + (size_t)b * 3 * NPTS;
    const float qx = base1[n], qy = base1[NPTS + n], qz = base1[2 * NPTS + n];
    const float qn = qx * qx + qy * qy + qz * qz;
    float d0 = 3.4e38f, d1 = 3.4e38f, d2 = 3.4e38f;
    int i0 = 0, i1 = 0, i2 = 0;
#pragma unroll 4
    for (int s = 0; s < SPTS; s++) {
        float d = qn + sn[s] - 2.f * (qx * sx[s] + qy * sy[s] + qz * sz[s]);
        if (d < d2) {
            if (d < d1) {
                if (d < d0) { d2 = d1; i2 = i1; d1 = d0; i1 = i0; d0 = d; i0 = s; }
                else        { d2 = d1; i2 = i1; d1 = d;  i1 = s; }
            } else          { d2 = d;  i2 = s; }
        }
    }
    const float r0 = 1.f / (d0 + 1e-8f);
    const float r1 = 1.f / (d1 + 1e-8f);
    const float r2 = 1.f / (d2 + 1e-8f);
    const float inv = 1.f / (r0 + r1 + r2);
    const int col = b * NPTS + n;
    g_idx[col * 3 + 0] = i0; g_idx[col * 3 + 1] = i1; g_idx[col * 3 + 2] = i2;
    g_w[col * 3 + 0] = r0 * inv; g_w[col * 3 + 1] = r1 * inv; g_w[col * 3 + 2] = r2 * inv;
}

// frag scatter to smem C tile [128][132] fp32 (8 warps, 32x64 warp tiles)
#define FRAGS_TO_CS() \
    __syncthreads(); \
    float* Cs = (float*)sm; \
    { \
        const int L = threadIdx.x & 31, w = threadIdx.x >> 5; \
        const int wm = w & 3, wn = w >> 2; \
        _Pragma("unroll") \
        for (int am = 0; am < 2; am++) \
            _Pragma("unroll") \
            for (int an = 0; an < 8; an++) { \
                const int m = wm * 32 + am * 16 + (L >> 2); \
                const int n = wn * 64 + an * 8 + ((L & 3) << 1); \
                Cs[m * 132 + n]           = acc[am][an][0]; \
                Cs[m * 132 + n + 1]       = acc[am][an][1]; \
                Cs[(m + 8) * 132 + n]     = acc[am][an][2]; \
                Cs[(m + 8) * 132 + n + 1] = acc[am][an][3]; \
            } \
    } \
    __syncthreads();

// ---------------- GEMM Z: tiles 128o x 128col, K=128 ----------------
__global__ __launch_bounds__(256, 2) void gemmZ_mma(const float* __restrict__ p2) {
    extern __shared__ __align__(16) char sm[];
    const int col0 = blockIdx.x * 128;
    const int kg = blockIdx.y >> 1;
    const int o0 = (blockIdx.y & 1) * 128;
    const int bb = col0 >> 10, sOff = col0 & 1023;

    float acc[2][8][4];
    mma_main<256, 1024, 4, false>(sm,
        g_W0Thi + (size_t)(128 + kg * 128) * 256 + o0,
        g_W0Tlo + (size_t)(128 + kg * 128) * 256 + o0,
        p2 + (size_t)bb * 131072 + sOff, nullptr, nullptr, acc);

    const int L = threadIdx.x & 31, w = threadIdx.x >> 5;
    const int wm = w & 3, wn = w >> 2;
#pragma unroll
    for (int am = 0; am < 2; am++)
#pragma unroll
        for (int an = 0; an < 8; an++) {
            const int m = o0 + wm * 32 + am * 16 + (L >> 2);
            const int n = col0 + wn * 64 + an * 8 + ((L & 3) << 1);
            float* z0 = g_Z + ((size_t)(kg * JCOLS + n)) * 256 + m;
            float* z1 = z0 + 256;
            z0[0] = acc[am][an][0];
            z1[0] = acc[am][an][1];
            z0[8] = acc[am][an][2];
            z1[8] = acc[am][an][3];
        }
}

// ---------------- GEMM Y: tiles 128m x 128col, M=256, K=128; gather+stats ----------------
__global__ __launch_bounds__(256, 2) void gemmY_mma(const float* __restrict__ p1,
                                                    const float* __restrict__ bias0) {
    extern __shared__ __align__(16) char sm[];
    const int col0 = blockIdx.x * 128;
    const int m0 = blockIdx.y * 128;
    const int bb = col0 >> 12, nOff = col0 & 4095;

    float acc[2][8][4];
    mma_main<256, 4096, 4, false>(sm,
        g_W0Thi + m0, g_W0Tlo + m0,
        p1 + (size_t)bb * 524288 + nOff, nullptr, nullptr, acc);

    FRAGS_TO_CS();

    const int t = threadIdx.x;
    const int tx = t & 15, ty = t >> 4;
    const int rowb = m0 + ty * 8;
    float a8[8][8];
#pragma unroll
    for (int i = 0; i < 8; i++) {
        float4 u0 = *(const float4*)&Cs[(ty * 8 + i) * 132 + tx * 8];
        float4 u1 = *(const float4*)&Cs[(ty * 8 + i) * 132 + tx * 8 + 4];
        a8[i][0] = u0.x; a8[i][1] = u0.y; a8[i][2] = u0.z; a8[i][3] = u0.w;
        a8[i][4] = u1.x; a8[i][5] = u1.y; a8[i][6] = u1.z; a8[i][7] = u1.w;
    }
    float bias[8];
#pragma unroll
    for (int i = 0; i < 8; i++) bias[i] = bias0[rowb + i];

#pragma unroll
    for (int j = 0; j < 8; j++) {
        const int col = col0 + tx * 8 + j;
        const int ia = g_idx[col * 3], ib = g_idx[col * 3 + 1], ic = g_idx[col * 3 + 2];
        const float wa = g_w[col * 3], wb = g_w[col * 3 + 1], wc = g_w[col * 3 + 2];
        const int jb = (col >> 12) << 10;
        const float* z0 = g_Z + ((size_t)(jb + ia)) * 256 + rowb;
        const float* z1 = g_Z + ((size_t)(JCOLS + jb + ib)) * 256 + rowb;
        const float* z2 = g_Z + ((size_t)(2 * JCOLS + jb + ic)) * 256 + rowb;
        float4 p0 = *(const float4*)z0, p0b = *(const float4*)(z0 + 4);
        float4 q0 = *(const float4*)z1, q0b = *(const float4*)(z1 + 4);
        float4 r0 = *(const float4*)z2, r0b = *(const float4*)(z2 + 4);
        a8[0][j] += bias[0] + wa * p0.x  + wb * q0.x  + wc * r0.x;
        a8[1][j] += bias[1] + wa * p0.y  + wb * q0.y  + wc * r0.y;
        a8[2][j] += bias[2] + wa * p0.z  + wb * q0.z  + wc * r0.z;
        a8[3][j] += bias[3] + wa * p0.w  + wb * q0.w  + wc * r0.w;
        a8[4][j] += bias[4] + wa * p0b.x + wb * q0b.x + wc * r0b.x;
        a8[5][j] += bias[5] + wa * p0b.y + wb * q0b.y + wc * r0b.y;
        a8[6][j] += bias[6] + wa * p0b.z + wb * q0b.z + wc * r0b.z;
        a8[7][j] += bias[7] + wa * p0b.w + wb * q0b.w + wc * r0b.w;
    }

    const int colT = col0 + tx * 8;
#pragma unroll
    for (int i = 0; i < 8; i++) {
        const int row = rowb + i;
        float* yp = g_Y + (size_t)row * COLS + colT;
        *(float4*)yp       = make_float4(a8[i][0], a8[i][1], a8[i][2], a8[i][3]);
        *(float4*)(yp + 4) = make_float4(a8[i][4], a8[i][5], a8[i][6], a8[i][7]);
        float s = 0.f, q = 0.f;
#pragma unroll
        for (int j = 0; j < 8; j++) { s += a8[i][j]; q += a8[i][j] * a8[i][j]; }
#pragma unroll
        for (int off = 8; off; off >>= 1) {
            s += __shfl_xor_sync(0xffffffffu, s, off);
            q += __shfl_xor_sync(0xffffffffu, q, off);
        }
        if ((t & 15) == 0) { atomicAdd(&g_sum0[row], s); atomicAdd(&g_sq0[row], q); }
    }
}

__global__ void finalize0(const float* __restrict__ gamma, const float* __restrict__ beta) {
    const int t = threadIdx.x;
    const float mean = g_sum0[t] * (1.f / COLS);
    const float var = g_sq0[t] * (1.f / COLS) - mean * mean;
    const float a = gamma[t] * rsqrtf(var + 1e-5f);
    g_a0[t] = a;
    g_c0[t] = beta[t] - mean * a;
}

// ---------------- GEMM O2: 128 x 128col, K=256; BN0+ReLU fused on B; stats ----------------
__global__ __launch_bounds__(256, 2) void gemmO2_mma(const float* __restrict__ bias1) {
    extern __shared__ __align__(16) char sm[];
    const int col0 = blockIdx.x * 128;

    float acc[2][8][4];
    mma_main<128, 65536, 8, true>(sm,
        g_W1Thi, g_W1Tlo,
        g_Y + col0, g_a0, g_c0, acc);

    FRAGS_TO_CS();

    const int t = threadIdx.x;
    const int tx = t & 15, ty = t >> 4;
    const int rowb = ty * 8;
    const int colT = col0 + tx * 8;
#pragma unroll
    for (int i = 0; i < 8; i++) {
        const int row = rowb + i;
        const float bias = bias1[row];
        float a8[8];
        float4 u0 = *(const float4*)&Cs[row * 132 + tx * 8];
        float4 u1 = *(const float4*)&Cs[row * 132 + tx * 8 + 4];
        a8[0] = u0.x + bias; a8[1] = u0.y + bias; a8[2] = u0.z + bias; a8[3] = u0.w + bias;
        a8[4] = u1.x + bias; a8[5] = u1.y + bias; a8[6] = u1.z + bias; a8[7] = u1.w + bias;
        float* op = g_O2 + (size_t)row * COLS + colT;
        *(float4*)op       = make_float4(a8[0], a8[1], a8[2], a8[3]);
        *(float4*)(op + 4) = make_float4(a8[4], a8[5], a8[6], a8[7]);
        float s = 0.f, q = 0.f;
#pragma unroll
        for (int j = 0; j < 8; j++) { s += a8[j]; q += a8[j] * a8[j]; }
#pragma unroll
        for (int off = 8; off; off >>= 1) {
            s += __shfl_xor_sync(0xffffffffu, s, off);
            q += __shfl_xor_sync(0xffffffffu, q, off);
        }
        if ((t & 15) == 0) { atomicAdd(&g_sum1[row], s); atomicAdd(&g_sq1[row], q); }
    }
}

__global__ void finalize1(const float* __restrict__ gamma, const float* __restrict__ beta) {
    const int t = threadIdx.x;
    const float mean = g_sum1[t] * (1.f / COLS);
    const float var = g_sq1[t] * (1.f / COLS) - mean * mean;
    const float a = gamma[t] * rsqrtf(var + 1e-5f);
    g_a1[t] = a;
    g_c1[t] = beta[t] - mean * a;
}

// ---------------- BN2 + ReLU + transpose store ----------------
__global__ void bnout_kernel(float* __restrict__ out) {
    const int idx = blockIdx.x * 256 + threadIdx.x;
    const int e = idx * 4;
    const int row = e >> 16;
    const int col = e & 65535;
    const int b = col >> 12, n = col & 4095;
    float4 v = *(const float4*)&g_O2[(size_t)row * COLS + col];
    const float a = g_a1[row], c = g_c1[row];
    float4 w;
    w.x = fmaxf(0.f, fmaf(a, v.x, c));
    w.y = fmaxf(0.f, fmaf(a, v.y, c));
    w.z = fmaxf(0.f, fmaf(a, v.z, c));
    w.w = fmaxf(0.f, fmaf(a, v.w, c));
    *(float4*)&out[((size_t)(b * 128 + row)) * 4096 + n] = w;
}

extern "C" void kernel_launch(void* const* d_in, const int* in_sizes, int n_in,
                              void* d_out, int out_size) {
    const float* xyz1 = (const float*)d_in[0];
    const float* xyz2 = (const float*)d_in[1];
    const float* p1   = (const float*)d_in[2];
    const float* p2   = (const float*)d_in[3];
    const float* w0   = (const float*)d_in[4];
    const float* b0   = (const float*)d_in[5];
    const float* g0   = (const float*)d_in[6];
    const float* be0  = (const float*)d_in[7];
    const float* w1   = (const float*)d_in[8];
    const float* b1   = (const float*)d_in[9];
    const float* g1   = (const float*)d_in[10];
    const float* be1  = (const float*)d_in[11];
    float* out = (float*)d_out;

    cudaFuncSetAttribute(gemmZ_mma, cudaFuncAttributeMaxDynamicSharedMemorySize, SMEM_BYTES);
    cudaFuncSetAttribute(gemmY_mma, cudaFuncAttributeMaxDynamicSharedMemorySize, SMEM_BYTES);
    cudaFuncSetAttribute(gemmO2_mma, cudaFuncAttributeMaxDynamicSharedMemorySize, SMEM_BYTES);

    prep_kernel<<<512, 256>>>(w0, w1);                              // 1
    knn_kernel<<<256, 256>>>(xyz1, xyz2);                           // 2
    gemmZ_mma<<<dim3(JCOLS / 128, 6), 256, SMEM_BYTES>>>(p2);       // 3
    gemmY_mma<<<dim3(COLS / 128, 2), 256, SMEM_BYTES>>>(p1, b0);    // 4
    finalize0<<<1, 256>>>(g0, be0);                                 // 5
    gemmO2_mma<<<COLS / 128, 256, SMEM_BYTES>>>(b1);                // 6
    finalize1<<<1, 128>>>(g1, be1);                                 // 7
    bnout_kernel<<<(COLS * 128 / 4) / 256, 256>>>(out);             // 8
}